// round 17
// baseline (speedup 1.0000x reference)
#include <cuda_runtime.h>
#include <cuda_bf16.h>
#include <stdint.h>

#define B_TOT 32768
#define N_DIM 512
#define SOLVE_ITERS 10
#define NSOLVE 32
#define NTOT 290
#define NPAIRS 10
#define TOT_STAGES 1024
#define CSPLIT 931                  // consumer stages [0,931) strided; producers [931,1024)
#define PROD_BASE 190               // producers: 190..289 (100 CTAs)
#define SOLVE_BASE 258              // solvers: 258..289 (solve, then produce)
#define NTASKS 2048                 // 16 rows per task
#define TASK_ROWS 16
#define NCHUNKS 32                  // 1024 rows per chunk = 64 tasks
#define TASKS_PER_CHUNK 64

// ------------- device scratch (no allocations; zero at load) -------------
__device__ __nv_bfloat16 g_R[(size_t)B_TOT * N_DIM];  // 32 MB bf16 r
__device__ float g_v[N_DIM];
__device__ float g_p[2][N_DIM];
__device__ float g_colsum[N_DIM];
__device__ double g_second;
__device__ unsigned g_bar_count, g_bar_gen;      // 32-CTA solve barrier
__device__ unsigned g_task;                      // production task-stealing counter
__device__ unsigned g_chunk_cnt[NCHUNKS];        // per-chunk completion counters
__device__ unsigned g_done, g_vcnt, g_v_ready;

__constant__ int c_pi[NPAIRS] = {0,0,0,0,1,1,1,2,2,3};
__constant__ int c_pj[NPAIRS] = {0,1,2,3,1,2,3,2,3,3};

// ---- volatile acquire load: spin-safe (compiler cannot hoist/delete) ----
__device__ __forceinline__ unsigned ldv_acq(const unsigned* p) {
    unsigned v;
    asm volatile("ld.global.acquire.gpu.u32 %0, [%1];" : "=r"(v) : "l"(p) : "memory");
    return v;
}
// ---- grid barrier among the 32 solve CTAs ----
__device__ __forceinline__ void solve_barrier(unsigned target) {
    __syncthreads();
    if (threadIdx.x == 0) {
        __threadfence();
        if (atomicAdd(&g_bar_count, 1u) == NSOLVE - 1) {
            atomicExch(&g_bar_count, 0u);
            __threadfence();
            atomicExch(&g_bar_gen, target);
        } else {
            while (ldv_acq(&g_bar_gen) < target) __nanosleep(20);
        }
        __threadfence();
    }
    __syncthreads();
}

// -------------------------- GEMM helpers --------------------------
__device__ __forceinline__ void cp16(void* smem, const void* gmem) {
    unsigned saddr = (unsigned)__cvta_generic_to_shared(smem);
    asm volatile("cp.async.cg.shared.global [%0], [%1], 16;\n" :: "r"(saddr), "l"(gmem));
}
__device__ __forceinline__ void ldsm4t(unsigned& d0, unsigned& d1, unsigned& d2, unsigned& d3,
                                       const __nv_bfloat16* p) {
    unsigned a = (unsigned)__cvta_generic_to_shared(p);
    asm volatile("ldmatrix.sync.aligned.m8n8.x4.trans.shared.b16 {%0,%1,%2,%3}, [%4];\n"
                 : "=r"(d0), "=r"(d1), "=r"(d2), "=r"(d3) : "r"(a));
}
__device__ __forceinline__ void mma16816(float* c, const unsigned* a, const unsigned* b) {
    asm volatile(
        "mma.sync.aligned.m16n8k16.row.col.f32.bf16.bf16.f32 "
        "{%0,%1,%2,%3}, {%4,%5,%6,%7}, {%8,%9}, {%0,%1,%2,%3};\n"
        : "+f"(c[0]), "+f"(c[1]), "+f"(c[2]), "+f"(c[3])
        : "r"(a[0]), "r"(a[1]), "r"(a[2]), "r"(a[3]), "r"(b[0]), "r"(b[1]));
}

// ==================== fully pipelined persistent kernel ====================
// CTAs 0..189   : consumers — gemm stages s = t + 19k (k<49) behind the chunk watermark
// CTAs 190..257 : producers — task-steal 16-row production tasks, then gemm [931,1024)
// CTAs 258..289 : Chebyshev solve, then join production, then gemm tail
__global__ void __launch_bounds__(256, 2) mono_k(const float* __restrict__ Gamma,
                                                 const float* __restrict__ SR,
                                                 const float* __restrict__ lsh,
                                                 const float* __restrict__ sig,
                                                 const int* __restrict__ kp,
                                                 float* __restrict__ out) {
    __shared__ __align__(16) __nv_bfloat16 smA[4][32][136];
    __shared__ __align__(16) __nv_bfloat16 smB[4][32][136];
    __shared__ float p_s[N_DIM];
    __shared__ double wsum[8];
    __shared__ int sh_task;
    __shared__ bool is_last;

    const int tid  = threadIdx.x;
    const int lane = tid & 31, wid = tid >> 5;
    const int cb   = (int)blockIdx.x;

    // ---------- producer: task-steal 16-row blocks; count chunk completions ----------
    auto produce_tasks = [&]() {
        const int tc = tid & 127;                 // column group (4 cols)
        const int half = tid >> 7;                // 0/1
        const size_t colOff = (size_t)tc * 4;
        float cs0 = 0.f, cs1 = 0.f, cs2 = 0.f, cs3 = 0.f;
        for (;;) {
            if (tid == 0) sh_task = (int)atomicAdd(&g_task, 1u);
            __syncthreads();
            const int t = sh_task;
            if (t >= NTASKS) break;
            const int r0w = t * TASK_ROWS;
            float4 av[8], bv[8];
#pragma unroll
            for (int u = 0; u < 8; u++) {         // 16 LDG.128 in flight per thread
                size_t off = (size_t)(r0w + u * 2 + half) * N_DIM + colOff;
                av[u] = __ldcs((const float4*)(lsh + off));
                bv[u] = __ldcs((const float4*)(sig + off));
            }
#pragma unroll
            for (int u = 0; u < 8; u++) {
                size_t off = (size_t)(r0w + u * 2 + half) * N_DIM + colOff;
                float r0 = __expf(bv[u].x - av[u].x), r1 = __expf(bv[u].y - av[u].y);
                float r2 = __expf(bv[u].z - av[u].z), r3 = __expf(bv[u].w - av[u].w);
                cs0 += r0; cs1 += r1; cs2 += r2; cs3 += r3;
                __nv_bfloat162 h0 = __floats2bfloat162_rn(r0, r1);
                __nv_bfloat162 h1 = __floats2bfloat162_rn(r2, r3);
                uint2 u2;
                u2.x = *reinterpret_cast<unsigned*>(&h0);
                u2.y = *reinterpret_cast<unsigned*>(&h1);
                *reinterpret_cast<uint2*>(&g_R[off]) = u2;
            }
            __threadfence();                      // release rows before counting
            __syncthreads();                      // also protects sh_task reuse
            if (tid == 0) atomicAdd(&g_chunk_cnt[t >> 6], 1u);
        }
        atomicAdd(&g_colsum[tc * 4 + 0], cs0);
        atomicAdd(&g_colsum[tc * 4 + 1], cs1);
        atomicAdd(&g_colsum[tc * 4 + 2], cs2);
        atomicAdd(&g_colsum[tc * 4 + 3], cs3);
    };

    int pair, sbeg, stride, ns;
    if (cb >= PROD_BASE) {
        if (cb >= SOLVE_BASE) {
            // ---------------- solve: v = Gamma^{-1} SR, Chebyshev, spec [1,5.5] ----------------
            const float lmin = 1.0f, lmax = 5.5f;
            const float theta = 0.5f * (lmax + lmin);
            const float delta = 0.5f * (lmax - lmin);
            const float sigma1 = theta / delta;
            float rho = 1.f / sigma1;
            const int row0 = (cb - SOLVE_BASE) * 16 + wid * 2;   // 2 rows per warp

            float4 gc[2][4];                      // register-cached Gamma rows
#pragma unroll
            for (int q = 0; q < 2; q++) {
                const float4* gr = (const float4*)(Gamma + (size_t)(row0 + q) * N_DIM);
#pragma unroll
                for (int tv = 0; tv < 4; tv++) gc[q][tv] = gr[lane + tv * 32];
            }
            float xv[2], rv[2], dv[2];
#pragma unroll
            for (int q = 0; q < 2; q++) {
                float b = SR[row0 + q];
                rv[q] = b; xv[q] = 0.f; dv[q] = b / theta;
                if (lane == 0) __stcg(&g_p[0][row0 + q], dv[q]);
            }
            unsigned gen = 0;
            for (int it = 0; it < SOLVE_ITERS; it++) {
                solve_barrier(++gen);
                int cur = it & 1;
                for (int j = tid; j < N_DIM; j += 256) p_s[j] = __ldcg(&g_p[cur][j]);
                __syncthreads();
#pragma unroll
                for (int q = 0; q < 2; q++) {
                    const float4* pr = (const float4*)p_s;
                    float acc = 0.f;
#pragma unroll
                    for (int tv = 0; tv < 4; tv++) {
                        float4 g  = gc[q][tv];
                        float4 p4 = pr[lane + tv * 32];
                        acc += g.x * p4.x + g.y * p4.y + g.z * p4.z + g.w * p4.w;
                    }
#pragma unroll
                    for (int o = 16; o > 0; o >>= 1) acc += __shfl_xor_sync(0xffffffffu, acc, o);
                    xv[q] += dv[q];
                    rv[q] -= acc;
                }
                float rho_n = 1.f / (2.f * sigma1 - rho);
#pragma unroll
                for (int q = 0; q < 2; q++) {
                    dv[q] = rho_n * rho * dv[q] + (2.f * rho_n / delta) * rv[q];
                    if (lane == 0 && it + 1 < SOLVE_ITERS) __stcg(&g_p[cur ^ 1][row0 + q], dv[q]);
                }
                rho = rho_n;
                __syncthreads();
            }
            if (lane == 0) {
                __stcg(&g_v[row0], xv[0]);
                __stcg(&g_v[row0 + 1], xv[1]);
            }
            __threadfence();
            __syncthreads();
            if (tid == 0) {
                if (atomicAdd(&g_vcnt, 1u) == NSOLVE - 1) {
                    __threadfence();
                    atomicExch(&g_v_ready, 1u);
                }
            }
        }
        produce_tasks();
        // producer gemm: tail stages [CSPLIT,1024), team g of 10 CTAs per pair
        const int b = cb - PROD_BASE;
        pair = b % NPAIRS;
        const int g = b / NPAIRS;                 // 0..9
        sbeg = CSPLIT + g; stride = 10;
        ns = (TOT_STAGES - CSPLIT - g + 9) / 10;  // 9 or 10
    } else {
        // consumer: strided stages behind the production watermark
        pair = cb % NPAIRS;
        const int t = cb / NPAIRS;                // 0..18
        sbeg = t; stride = 19; ns = 49;           // covers [0,931)
    }

    const int ti = c_pi[pair] * 128, tj = c_pj[pair] * 128;
    const bool diag = (ti == tj);
    const int wi = wid >> 2, wj = wid & 3;        // warp tile 64(i) x 32(j)

    float acc[4][4][4];
#pragma unroll
    for (int a = 0; a < 4; a++)
#pragma unroll
        for (int b2 = 0; b2 < 4; b2++)
#pragma unroll
            for (int e = 0; e < 4; e++) acc[a][b2][e] = 0.f;

    auto load_stage = [&](int s, int buf) {
        int kbase = s * 32;
#pragma unroll
        for (int qq = 0; qq < 2; qq++) {
            int idx = tid + qq * 256;
            int row = idx >> 4, ch = idx & 15;
            const __nv_bfloat16* gbase = g_R + (size_t)(kbase + row) * N_DIM + ch * 8;
            cp16(&smA[buf][row][ch * 8], gbase + ti);
            if (!diag) cp16(&smB[buf][row][ch * 8], gbase + tj);
        }
    };
    // tid0 spins until the chunk containing stage s is fully produced
    auto wait_stage = [&](int s) {
        if (tid == 0) {
            const unsigned* c = &g_chunk_cnt[s >> 5];
            while (ldv_acq(c) < TASKS_PER_CHUNK) __nanosleep(30);
        }
    };

    // prologue: chunks are needed monotonically; waiting on stage sbeg+2*stride covers all 3
    wait_stage(sbeg + 2 * stride);
    __syncthreads();
    load_stage(sbeg + 0 * stride, 0); asm volatile("cp.async.commit_group;\n");
    load_stage(sbeg + 1 * stride, 1); asm volatile("cp.async.commit_group;\n");
    load_stage(sbeg + 2 * stride, 2); asm volatile("cp.async.commit_group;\n");

    const __nv_bfloat16 (*smBsel)[32][136] = diag ? smA : smB;
    const int g = lane >> 3, r = lane & 7;
    for (int s = 0; s < ns; s++) {
        asm volatile("cp.async.wait_group 2;\n");   // stage s resident
        if (s + 3 < ns) wait_stage(sbeg + (s + 3) * stride);
        __syncthreads();                            // buf (s+3)&3 free for rewrite
        if (s + 3 < ns) load_stage(sbeg + (s + 3) * stride, (s + 3) & 3);
        asm volatile("cp.async.commit_group;\n");   // empty commit at tail keeps count
        const int buf = s & 3;
#pragma unroll
        for (int ks = 0; ks < 2; ks++) {
            int kk = ks * 16;
            unsigned afr[4][4], bfr[4][2];
#pragma unroll
            for (int mt = 0; mt < 4; mt++) {
                int i0 = wi * 64 + mt * 16;
                const __nv_bfloat16* p = &smA[buf][kk + ((g >> 1) << 3) + r][i0 + ((g & 1) << 3)];
                ldsm4t(afr[mt][0], afr[mt][1], afr[mt][2], afr[mt][3], p);
            }
#pragma unroll
            for (int n2 = 0; n2 < 2; n2++) {
                int j0 = wj * 32 + n2 * 16;
                const __nv_bfloat16* p = &smBsel[buf][kk + ((g & 1) << 3) + r][j0 + ((g >> 1) << 3)];
                unsigned d0, d1, d2, d3;
                ldsm4t(d0, d1, d2, d3, p);
                bfr[n2 * 2][0] = d0; bfr[n2 * 2][1] = d1;
                bfr[n2 * 2 + 1][0] = d2; bfr[n2 * 2 + 1][1] = d3;
            }
#pragma unroll
            for (int mt = 0; mt < 4; mt++)
#pragma unroll
                for (int nt = 0; nt < 4; nt++) mma16816(acc[mt][nt], afr[mt], bfr[nt]);
        }
    }

    // ---- v (solvers finish ~20us; earliest epilogue ~60us; proven spin) ----
    if (tid == 0) { while (ldv_acq(&g_v_ready) == 0u) __nanosleep(20); }
    __syncthreads();
    for (int j = tid; j < N_DIM; j += 256) p_s[j] = __ldcg(&g_v[j]);
    __syncthreads();

    // epilogue: partial = sum Gamma_ij v_i v_j C_ij over this CTA's tile
    float partf = 0.f;
#pragma unroll
    for (int mt = 0; mt < 4; mt++) {
        int ibase = ti + wi * 64 + mt * 16 + (lane >> 2);
#pragma unroll
        for (int nt = 0; nt < 4; nt++) {
            int jbase = tj + wj * 32 + nt * 8 + 2 * (lane & 3);
#pragma unroll
            for (int e = 0; e < 4; e++) {
                int i = ibase + ((e >> 1) << 3);
                int j = jbase + (e & 1);
                partf += acc[mt][nt][e] * Gamma[(size_t)i * N_DIM + j] * p_s[i] * p_s[j];
            }
        }
    }
#pragma unroll
    for (int o = 16; o > 0; o >>= 1) partf += __shfl_xor_sync(0xffffffffu, partf, o);
    if (lane == 0) wsum[wid] = (double)partf;
    __syncthreads();
    if (tid == 0) {
        double sv = 0.0;
        for (int x = 0; x < 8; x++) sv += wsum[x];
        if (ti != tj) sv *= 2.0;   // off-diagonal tiles counted twice (symmetry)
        atomicAdd(&g_second, sv);
        __threadfence();
        unsigned d = atomicAdd(&g_done, 1u);
        is_last = (d == NTOT - 1);
    }
    __syncthreads();

    // ---------------- last CTA finalizes + resets for next replay ----------------
    if (is_last) {
        double term = 0.0;
        for (int j = tid; j < N_DIM; j += 256)
            term += (double)__ldcg(&g_colsum[j]) * (double)p_s[j] * (double)SR[j];
#pragma unroll
        for (int o = 16; o > 0; o >>= 1) term += __shfl_xor_sync(0xffffffffu, term, o);
        if (lane == 0) wsum[wid] = term;
        __syncthreads();
        if (tid == 0) {
            double sf = 0.0;
            for (int x = 0; x < 8; x++) sf += wsum[x];
            double sec = atomicAdd(&g_second, 0.0);   // writers fenced before g_done
            double k = (double)kp[0];
            out[0] = (float)((0.5 * sec - sf) / ((double)B_TOT * k));
        }
        __syncthreads();
        // self-clean device state for the next graph replay
        for (int j = tid; j < N_DIM; j += 256) g_colsum[j] = 0.f;
        if (tid < NCHUNKS) g_chunk_cnt[tid] = 0u;
        if (tid == 0) {
            g_second = 0.0;
            g_task = 0u;
            g_done = 0u; g_vcnt = 0u; g_v_ready = 0u;
            g_bar_count = 0u; g_bar_gen = 0u;
        }
    }
}

// ------------------------------ launch ------------------------------
extern "C" void kernel_launch(void* const* d_in, const int* in_sizes, int n_in,
                              void* d_out, int out_size) {
    const float* lsh = (const float*)d_in[0];
    const float* sig = (const float*)d_in[1];
    const float* SR  = (const float*)d_in[2];
    const float* Gam = (const float*)d_in[3];
    const int*   kp  = (const int*)d_in[4];

    mono_k<<<NTOT, 256>>>(Gam, SR, lsh, sig, kp, (float*)d_out);
}